// round 3
// baseline (speedup 1.0000x reference)
#include <cuda_runtime.h>
#include <cuda_bf16.h>

#define MAXN 100000
#define MAXE 1600000
#define MAXF 128

typedef unsigned long long u64;

// ---- packed f32x2 helpers (FFMA2 — ptxas never emits this from C++) ----
__device__ __forceinline__ void ffma2(u64& d, u64 a, u64 b) {
    asm("fma.rn.f32x2 %0, %1, %2, %0;" : "+l"(d) : "l"(a), "l"(b));
}
__device__ __forceinline__ u64 pk2(float lo, float hi) {
    u64 r; asm("mov.b64 %0, {%1, %2};" : "=l"(r) : "f"(lo), "f"(hi)); return r;
}
__device__ __forceinline__ float2 upk2(u64 v) {
    float2 r; asm("mov.b64 {%0, %1}, %2;" : "=f"(r.x), "=f"(r.y) : "l"(v)); return r;
}

// ---------------- scratch (device globals; no cudaMalloc allowed) ----------------
__device__ float g_bufA[MAXN * MAXF];
__device__ float g_bufB[MAXN * MAXF];
__device__ int   g_deg[MAXN];
__device__ float g_dinv[MAXN];
__device__ int   g_rowptr[MAXN + 1];
__device__ int   g_fill[MAXN];
__device__ int2  g_edge[MAXE];          // (src, __float_as_int(norm)) packed
__device__ int   g_blocksum[64];
__device__ int   g_blockoff[64];

// ---------------- preprocessing ----------------
__global__ void zero_kernel(int N) {
    int i = blockIdx.x * blockDim.x + threadIdx.x;
    if (i < N) { g_deg[i] = 0; g_fill[i] = 0; }
}

__global__ void deg_kernel(const int* __restrict__ dst, int E) {
    int e = blockIdx.x * blockDim.x + threadIdx.x;
    if (e < E) atomicAdd(&g_deg[dst[e]], 1);
}

// ---- 3-phase exclusive scan of g_deg -> g_rowptr ----
__global__ void scan1_kernel(int N) {
    const int T = 1024, EL = 4;
    int t = threadIdx.x;
    int base = blockIdx.x * (T * EL) + t * EL;
    int v[EL];
    int s = 0;
#pragma unroll
    for (int j = 0; j < EL; j++) {
        int i = base + j;
        v[j] = (i < N) ? g_deg[i] : 0;
        s += v[j];
    }
    __shared__ int sh[T];
    sh[t] = s;
    __syncthreads();
    for (int o = 1; o < T; o <<= 1) {
        int u = (t >= o) ? sh[t - o] : 0;
        __syncthreads();
        sh[t] += u;
        __syncthreads();
    }
    int run = (t == 0) ? 0 : sh[t - 1];
#pragma unroll
    for (int j = 0; j < EL; j++) {
        int i = base + j;
        if (i < N) g_rowptr[i] = run;
        run += v[j];
    }
    if (t == T - 1) g_blocksum[blockIdx.x] = sh[T - 1];
}

__global__ void scan2_kernel(int NB, int N) {
    int t = threadIdx.x;
    int x = (t < NB) ? g_blocksum[t] : 0;
    int v = x;
    for (int o = 1; o < 32; o <<= 1) {
        int u = __shfl_up_sync(0xFFFFFFFFu, v, o);
        if (t >= o) v += u;
    }
    if (t < NB) g_blockoff[t] = v - x;
    if (t == NB - 1) g_rowptr[N] = v;
}

__global__ void scan3_kernel(int N) {
    int i = blockIdx.x * blockDim.x + threadIdx.x;
    if (i < N) {
        g_rowptr[i] += g_blockoff[i >> 12];
        g_dinv[i] = rsqrtf((float)g_deg[i] + 1.0f);
    }
}

__global__ void scatter_kernel(const int* __restrict__ src, const int* __restrict__ dst, int E) {
    int e = blockIdx.x * blockDim.x + threadIdx.x;
    if (e >= E) return;
    int s = src[e], d = dst[e];
    int pos = g_rowptr[d] + atomicAdd(&g_fill[d], 1);
    g_edge[pos] = make_int2(s, __float_as_int(g_dinv[s] * g_dinv[d]));
}

// ---------------- GEMM (FFMA2): out[n][f] = sum_k in[n][k]*W[k][f] ----------------
template <int K, int F, int NPG, bool BIAS, bool RELU>
__global__ void __launch_bounds__(128) gemm_kernel(
        const float* __restrict__ in, const float* __restrict__ W,
        const float* __restrict__ b, float* __restrict__ out, int N) {
    constexpr int GROUPS = 128 / F;
    constexpr int NT = NPG * GROUPS;
    __shared__ float sx[NT * K];
    int base = blockIdx.x * NT;
    for (int i = threadIdx.x; i < NT * K; i += 128) {
        int r = i / K, c = i % K;
        int n = base + r;
        sx[i] = (n < N) ? in[n * K + c] : 0.0f;
    }
    __syncthreads();
    int f = threadIdx.x % F;
    int g = threadIdx.x / F;

    if constexpr (K % 4 == 0) {
        u64 acc01[NPG], acc23[NPG];
#pragma unroll
        for (int j = 0; j < NPG; j++) { acc01[j] = 0ull; acc23[j] = 0ull; }
        for (int k = 0; k < K; k += 4) {
            float w0 = W[(k + 0) * F + f];
            float w1 = W[(k + 1) * F + f];
            float w2 = W[(k + 2) * F + f];
            float w3 = W[(k + 3) * F + f];
            u64 wp01 = pk2(w0, w1);
            u64 wp23 = pk2(w2, w3);
#pragma unroll
            for (int j = 0; j < NPG; j++) {
                const float4 x4 = *reinterpret_cast<const float4*>(&sx[(g * NPG + j) * K + k]);
                ffma2(acc01[j], pk2(x4.x, x4.y), wp01);
                ffma2(acc23[j], pk2(x4.z, x4.w), wp23);
            }
        }
        float bv = BIAS ? b[f] : 0.0f;
#pragma unroll
        for (int j = 0; j < NPG; j++) {
            int n = base + g * NPG + j;
            if (n < N) {
                float2 a = upk2(acc01[j]);
                float2 c = upk2(acc23[j]);
                float v = (a.x + a.y) + (c.x + c.y) + bv;
                if (RELU) v = fmaxf(v, 0.0f);
                out[n * F + f] = v;
            }
        }
    } else {
        float acc[NPG];
#pragma unroll
        for (int j = 0; j < NPG; j++) acc[j] = 0.0f;
        for (int k = 0; k < K; k++) {
            float wv = W[k * F + f];
#pragma unroll
            for (int j = 0; j < NPG; j++)
                acc[j] = fmaf(sx[(g * NPG + j) * K + k], wv, acc[j]);
        }
        float bv = BIAS ? b[f] : 0.0f;
#pragma unroll
        for (int j = 0; j < NPG; j++) {
            int n = base + g * NPG + j;
            if (n < N) {
                float v = acc[j] + bv;
                if (RELU) v = fmaxf(v, 0.0f);
                out[n * F + f] = v;
            }
        }
    }
}

// ---------------- Aggregation (float4 + FFMA2 + packed edges) ----------------
template <int F, bool BIAS, bool RELU>
__global__ void agg4_kernel(const float* __restrict__ h, float* __restrict__ out,
                            const float* __restrict__ b, int N) {
    constexpr int TPN = F / 4;
    constexpr int NPB = 128 / TPN;
    int n = blockIdx.x * NPB + threadIdx.x / TPN;
    if (n >= N) return;
    int f4 = threadIdx.x % TPN;
    const float4* __restrict__ h4 = (const float4*)h;
    float di = g_dinv[n];
    float s0 = di * di;
    float4 v = h4[n * TPN + f4];
    u64 xy0 = pk2(v.x * s0, v.y * s0), zw0 = pk2(v.z * s0, v.w * s0);
    u64 xy1 = 0ull, zw1 = 0ull;
    int beg = g_rowptr[n], end = g_rowptr[n + 1];
    int j = beg;
    for (; j + 1 < end; j += 2) {
        int2 eA = g_edge[j];
        int2 eB = g_edge[j + 1];
        float4 a = h4[eA.x * TPN + f4];
        float4 c = h4[eB.x * TPN + f4];
        float nA = __int_as_float(eA.y);
        float nB = __int_as_float(eB.y);
        u64 nAp = pk2(nA, nA), nBp = pk2(nB, nB);
        ffma2(xy0, pk2(a.x, a.y), nAp);
        ffma2(zw0, pk2(a.z, a.w), nAp);
        ffma2(xy1, pk2(c.x, c.y), nBp);
        ffma2(zw1, pk2(c.z, c.w), nBp);
    }
    if (j < end) {
        int2 eA = g_edge[j];
        float4 a = h4[eA.x * TPN + f4];
        float nA = __int_as_float(eA.y);
        u64 nAp = pk2(nA, nA);
        ffma2(xy0, pk2(a.x, a.y), nAp);
        ffma2(zw0, pk2(a.z, a.w), nAp);
    }
    float2 rxy0 = upk2(xy0), rzw0 = upk2(zw0);
    float2 rxy1 = upk2(xy1), rzw1 = upk2(zw1);
    float4 r = make_float4(rxy0.x + rxy1.x, rxy0.y + rxy1.y,
                           rzw0.x + rzw1.x, rzw0.y + rzw1.y);
    if (BIAS) {
        const float4 bv = *reinterpret_cast<const float4*>(b + f4 * 4);
        r.x += bv.x; r.y += bv.y; r.z += bv.z; r.w += bv.w;
    }
    if (RELU) {
        r.x = fmaxf(r.x, 0.f); r.y = fmaxf(r.y, 0.f);
        r.z = fmaxf(r.z, 0.f); r.w = fmaxf(r.w, 0.f);
    }
    ((float4*)out)[n * TPN + f4] = r;
}

// scalar aggregation for F=2 (layer-1 input)
__global__ void agg2_kernel(const float* __restrict__ h, float* __restrict__ out, int N) {
    int n = blockIdx.x * 64 + threadIdx.x / 2;
    if (n >= N) return;
    int f = threadIdx.x % 2;
    float di = g_dinv[n];
    float acc = h[n * 2 + f] * di * di;
    int beg = g_rowptr[n], end = g_rowptr[n + 1];
    for (int j = beg; j < end; j++) {
        int2 e = g_edge[j];
        acc = fmaf(h[e.x * 2 + f], __int_as_float(e.y), acc);
    }
    out[n * 2 + f] = acc;
}

// ---------------- final linear: out[n] = x[n,0:64] . Wl + bl ----------------
__global__ void linear_kernel(const float* __restrict__ x, const float* __restrict__ Wl,
                              const float* __restrict__ bl, float* __restrict__ out, int N) {
    int warp = (blockIdx.x * blockDim.x + threadIdx.x) >> 5;
    int lane = threadIdx.x & 31;
    if (warp >= N) return;
    float v = x[warp * 64 + lane] * Wl[lane] + x[warp * 64 + 32 + lane] * Wl[32 + lane];
#pragma unroll
    for (int o = 16; o; o >>= 1) v += __shfl_xor_sync(0xFFFFFFFFu, v, o);
    if (lane == 0) out[warp] = v + bl[0];
}

// ---------------- launch ----------------
extern "C" void kernel_launch(void* const* d_in, const int* in_sizes, int n_in,
                              void* d_out, int out_size) {
    const float* x  = (const float*)d_in[0];
    const int*   ei = (const int*)d_in[1];
    int wb = n_in - 12;
    const float* W1 = (const float*)d_in[wb + 0];
    const float* b1 = (const float*)d_in[wb + 1];
    const float* W2 = (const float*)d_in[wb + 2];
    const float* b2 = (const float*)d_in[wb + 3];
    const float* W3 = (const float*)d_in[wb + 4];
    const float* b3 = (const float*)d_in[wb + 5];
    const float* W4 = (const float*)d_in[wb + 6];
    const float* b4 = (const float*)d_in[wb + 7];
    const float* W5 = (const float*)d_in[wb + 8];
    const float* b5 = (const float*)d_in[wb + 9];
    const float* Wl = (const float*)d_in[wb + 10];
    const float* bl = (const float*)d_in[wb + 11];
    float* out = (float*)d_out;

    int N = in_sizes[0] / 2;
    int E = in_sizes[1] / 2;
    const int* src = ei;
    const int* dst = ei + E;

    float *bufA, *bufB;
    cudaGetSymbolAddress((void**)&bufA, g_bufA);
    cudaGetSymbolAddress((void**)&bufB, g_bufB);

    // ---- build normalized CSR (dst-sorted edges) ----
    zero_kernel<<<(N + 255) / 256, 256>>>(N);
    deg_kernel<<<(E + 255) / 256, 256>>>(dst, E);
    int NB = (N + 4095) / 4096;
    scan1_kernel<<<NB, 1024>>>(N);
    scan2_kernel<<<1, 32>>>(NB, N);
    scan3_kernel<<<(N + 1023) / 1024, 1024>>>(N);
    scatter_kernel<<<(E + 255) / 256, 256>>>(src, dst, E);

    // ---- layer 1: t = A x (F=2) ; x1 = relu(t W1 + b1) ----
    agg2_kernel<<<(N + 63) / 64, 128>>>(x, bufB, N);
    gemm_kernel<2, 128, 8, true, true><<<(N + 7) / 8, 128>>>(bufB, W1, b1, bufA, N);

    // ---- layer 2: t = A x1 (F=128) ; x2 = relu(t W2 + b2) ----
    agg4_kernel<128, false, false><<<(N + 3) / 4, 128>>>(bufA, bufB, nullptr, N);
    gemm_kernel<128, 128, 16, true, true><<<(N + 15) / 16, 128>>>(bufB, W2, b2, bufA, N);

    // ---- layer 3: t = x2 W3 (no bias) ; x3 = relu(A t + b3) (F=32) ----
    gemm_kernel<128, 32, 8, false, false><<<(N + 31) / 32, 128>>>(bufA, W3, nullptr, bufB, N);
    agg4_kernel<32, true, true><<<(N + 15) / 16, 128>>>(bufB, bufA, b3, N);

    // ---- layer 4: t = A x3 (F=32) ; x4 = relu(t W4 + b4) ----
    agg4_kernel<32, false, false><<<(N + 15) / 16, 128>>>(bufA, bufB, nullptr, N);
    gemm_kernel<32, 32, 8, true, true><<<(N + 31) / 32, 128>>>(bufB, W4, b4, bufA, N);

    // ---- layer 5: t = A x4 (F=32) ; x5 = relu(t W5 + b5) (F=64) ----
    agg4_kernel<32, false, false><<<(N + 15) / 16, 128>>>(bufA, bufB, nullptr, N);
    gemm_kernel<32, 64, 8, true, true><<<(N + 15) / 16, 128>>>(bufB, W5, b5, bufA, N);

    // ---- final linear 64 -> 1 ----
    linear_kernel<<<(N * 32 + 255) / 256, 256>>>(bufA, Wl, bl, out, N);
}

// round 4
// speedup vs baseline: 1.0398x; 1.0398x over previous
#include <cuda_runtime.h>
#include <cuda_bf16.h>

#define MAXN 100000
#define MAXE 1600000
#define MAXF 128

typedef unsigned long long u64;

// ---- packed f32x2 helpers ----
__device__ __forceinline__ void ffma2(u64& d, u64 a, u64 b) {
    asm("fma.rn.f32x2 %0, %1, %2, %0;" : "+l"(d) : "l"(a), "l"(b));
}
__device__ __forceinline__ u64 pk2(float lo, float hi) {
    u64 r; asm("mov.b64 %0, {%1, %2};" : "=l"(r) : "f"(lo), "f"(hi)); return r;
}
__device__ __forceinline__ float2 upk2(u64 v) {
    float2 r; asm("mov.b64 {%0, %1}, %2;" : "=f"(r.x), "=f"(r.y) : "l"(v)); return r;
}
// 16B shared load as two aligned u64 pairs — no packing MOVs.
__device__ __forceinline__ void lds_v2u64(u64& a, u64& b, const float* p) {
    unsigned sa = (unsigned)__cvta_generic_to_shared(p);
    asm("ld.shared.v2.u64 {%0, %1}, [%2];" : "=l"(a), "=l"(b) : "r"(sa));
}

// ---------------- scratch (device globals; no cudaMalloc allowed) ----------------
__device__ float g_bufA[MAXN * MAXF];
__device__ float g_bufB[MAXN * MAXF];
__device__ int   g_deg[MAXN];
__device__ float g_dinv[MAXN];
__device__ int   g_rowptr[MAXN + 1];
__device__ int   g_fill[MAXN];
__device__ int2  g_edge[MAXE];          // (src, __float_as_int(norm))
__device__ int   g_blocksum[64];
__device__ int   g_blockoff[64];

// ---------------- preprocessing ----------------
__global__ void deg_kernel(const int* __restrict__ dst, int E) {
    int e = blockIdx.x * blockDim.x + threadIdx.x;
    if (e < E) atomicAdd(&g_deg[dst[e]], 1);
}

__global__ void scan1_kernel(int N) {
    const int T = 1024, EL = 4;
    int t = threadIdx.x;
    int base = blockIdx.x * (T * EL) + t * EL;
    int v[EL];
    int s = 0;
#pragma unroll
    for (int j = 0; j < EL; j++) {
        int i = base + j;
        v[j] = (i < N) ? g_deg[i] : 0;
        s += v[j];
    }
    __shared__ int sh[T];
    sh[t] = s;
    __syncthreads();
    for (int o = 1; o < T; o <<= 1) {
        int u = (t >= o) ? sh[t - o] : 0;
        __syncthreads();
        sh[t] += u;
        __syncthreads();
    }
    int run = (t == 0) ? 0 : sh[t - 1];
#pragma unroll
    for (int j = 0; j < EL; j++) {
        int i = base + j;
        if (i < N) g_rowptr[i] = run;
        run += v[j];
    }
    if (t == T - 1) g_blocksum[blockIdx.x] = sh[T - 1];
}

__global__ void scan2_kernel(int NB, int N) {
    int t = threadIdx.x;
    int x = (t < NB) ? g_blocksum[t] : 0;
    int v = x;
    for (int o = 1; o < 32; o <<= 1) {
        int u = __shfl_up_sync(0xFFFFFFFFu, v, o);
        if (t >= o) v += u;
    }
    if (t < NB) g_blockoff[t] = v - x;
    if (t == NB - 1) g_rowptr[N] = v;
}

__global__ void scan3_kernel(int N) {
    int i = blockIdx.x * blockDim.x + threadIdx.x;
    if (i < N) {
        g_rowptr[i] += g_blockoff[i >> 12];
        g_dinv[i] = rsqrtf((float)g_deg[i] + 1.0f);
    }
}

__global__ void scatter_kernel(const int* __restrict__ src, const int* __restrict__ dst, int E) {
    int e = blockIdx.x * blockDim.x + threadIdx.x;
    if (e >= E) return;
    int s = src[e], d = dst[e];
    int pos = g_rowptr[d] + atomicAdd(&g_fill[d], 1);
    g_edge[pos] = make_int2(s, __float_as_int(g_dinv[s] * g_dinv[d]));
}

// ---------------- GEMM: out[n][f] = sum_k in[n][k]*W[k][f] (+b, relu opt) ----------------
// FFMA2 path with ld.shared.v2.u64 — 3 issues per (node, k-quad) vs 5 scalar.
template <int K, int F, int NPG, bool BIAS, bool RELU>
__global__ void __launch_bounds__(128) gemm_kernel(
        const float* __restrict__ in, const float* __restrict__ W,
        const float* __restrict__ b, float* __restrict__ out, int N) {
    constexpr int GROUPS = 128 / F;
    constexpr int NT = NPG * GROUPS;
    __shared__ float sx[NT * K];
    int base = blockIdx.x * NT;
    for (int i = threadIdx.x; i < NT * K; i += 128) {
        int r = i / K, c = i % K;
        int n = base + r;
        sx[i] = (n < N) ? in[n * K + c] : 0.0f;
    }
    __syncthreads();
    int f = threadIdx.x % F;
    int g = threadIdx.x / F;

    if constexpr (K % 4 == 0) {
        u64 acc01[NPG], acc23[NPG];
#pragma unroll
        for (int j = 0; j < NPG; j++) { acc01[j] = 0ull; acc23[j] = 0ull; }
        for (int k = 0; k < K; k += 4) {
            u64 wp01 = pk2(W[(k + 0) * F + f], W[(k + 1) * F + f]);
            u64 wp23 = pk2(W[(k + 2) * F + f], W[(k + 3) * F + f]);
#pragma unroll
            for (int j = 0; j < NPG; j++) {
                u64 x01, x23;
                lds_v2u64(x01, x23, &sx[(g * NPG + j) * K + k]);
                ffma2(acc01[j], x01, wp01);
                ffma2(acc23[j], x23, wp23);
            }
        }
        float bv = BIAS ? b[f] : 0.0f;
#pragma unroll
        for (int j = 0; j < NPG; j++) {
            int n = base + g * NPG + j;
            if (n < N) {
                float2 a = upk2(acc01[j]);
                float2 c = upk2(acc23[j]);
                float v = (a.x + a.y) + (c.x + c.y) + bv;
                if (RELU) v = fmaxf(v, 0.0f);
                out[n * F + f] = v;
            }
        }
    } else {
        float acc[NPG];
#pragma unroll
        for (int j = 0; j < NPG; j++) acc[j] = 0.0f;
        for (int k = 0; k < K; k++) {
            float wv = W[k * F + f];
#pragma unroll
            for (int j = 0; j < NPG; j++)
                acc[j] = fmaf(sx[(g * NPG + j) * K + k], wv, acc[j]);
        }
        float bv = BIAS ? b[f] : 0.0f;
#pragma unroll
        for (int j = 0; j < NPG; j++) {
            int n = base + g * NPG + j;
            if (n < N) {
                float v = acc[j] + bv;
                if (RELU) v = fmaxf(v, 0.0f);
                out[n * F + f] = v;
            }
        }
    }
}

// ---------------- Aggregation (float4, scalar FFMA, packed int2 edges) ----------------
template <int F, bool BIAS, bool RELU>
__global__ void agg4_kernel(const float* __restrict__ h, float* __restrict__ out,
                            const float* __restrict__ b, int N) {
    constexpr int TPN = F / 4;
    constexpr int NPB = 128 / TPN;
    int n = blockIdx.x * NPB + threadIdx.x / TPN;
    if (n >= N) return;
    int f4 = threadIdx.x % TPN;
    const float4* __restrict__ h4 = (const float4*)h;
    float di = g_dinv[n];
    float s0 = di * di;
    float4 v = h4[n * TPN + f4];
    float4 acc0 = make_float4(v.x * s0, v.y * s0, v.z * s0, v.w * s0);
    float4 acc1 = make_float4(0.f, 0.f, 0.f, 0.f);
    int beg = g_rowptr[n], end = g_rowptr[n + 1];
    int j = beg;
    for (; j + 1 < end; j += 2) {
        int2 eA = g_edge[j];
        int2 eB = g_edge[j + 1];
        float4 a = h4[eA.x * TPN + f4];
        float4 c = h4[eB.x * TPN + f4];
        float nA = __int_as_float(eA.y);
        float nB = __int_as_float(eB.y);
        acc0.x = fmaf(a.x, nA, acc0.x);
        acc0.y = fmaf(a.y, nA, acc0.y);
        acc0.z = fmaf(a.z, nA, acc0.z);
        acc0.w = fmaf(a.w, nA, acc0.w);
        acc1.x = fmaf(c.x, nB, acc1.x);
        acc1.y = fmaf(c.y, nB, acc1.y);
        acc1.z = fmaf(c.z, nB, acc1.z);
        acc1.w = fmaf(c.w, nB, acc1.w);
    }
    if (j < end) {
        int2 eA = g_edge[j];
        float4 a = h4[eA.x * TPN + f4];
        float nA = __int_as_float(eA.y);
        acc0.x = fmaf(a.x, nA, acc0.x);
        acc0.y = fmaf(a.y, nA, acc0.y);
        acc0.z = fmaf(a.z, nA, acc0.z);
        acc0.w = fmaf(a.w, nA, acc0.w);
    }
    float4 r = make_float4(acc0.x + acc1.x, acc0.y + acc1.y,
                           acc0.z + acc1.z, acc0.w + acc1.w);
    if (BIAS) {
        const float4 bv = *reinterpret_cast<const float4*>(b + f4 * 4);
        r.x += bv.x; r.y += bv.y; r.z += bv.z; r.w += bv.w;
    }
    if (RELU) {
        r.x = fmaxf(r.x, 0.f); r.y = fmaxf(r.y, 0.f);
        r.z = fmaxf(r.z, 0.f); r.w = fmaxf(r.w, 0.f);
    }
    ((float4*)out)[n * TPN + f4] = r;
}

// scalar aggregation for F=2 (layer-1 input)
__global__ void agg2_kernel(const float* __restrict__ h, float* __restrict__ out, int N) {
    int n = blockIdx.x * 64 + threadIdx.x / 2;
    if (n >= N) return;
    int f = threadIdx.x % 2;
    float di = g_dinv[n];
    float acc = h[n * 2 + f] * di * di;
    int beg = g_rowptr[n], end = g_rowptr[n + 1];
    for (int j = beg; j < end; j++) {
        int2 e = g_edge[j];
        acc = fmaf(h[e.x * 2 + f], __int_as_float(e.y), acc);
    }
    out[n * 2 + f] = acc;
}

// ---------------- final linear: out[n] = x[n,0:64] . Wl + bl ----------------
__global__ void linear_kernel(const float* __restrict__ x, const float* __restrict__ Wl,
                              const float* __restrict__ bl, float* __restrict__ out, int N) {
    int warp = (blockIdx.x * blockDim.x + threadIdx.x) >> 5;
    int lane = threadIdx.x & 31;
    if (warp >= N) return;
    float v = x[warp * 64 + lane] * Wl[lane] + x[warp * 64 + 32 + lane] * Wl[32 + lane];
#pragma unroll
    for (int o = 16; o; o >>= 1) v += __shfl_xor_sync(0xFFFFFFFFu, v, o);
    if (lane == 0) out[warp] = v + bl[0];
}

// ---------------- launch ----------------
extern "C" void kernel_launch(void* const* d_in, const int* in_sizes, int n_in,
                              void* d_out, int out_size) {
    const float* x  = (const float*)d_in[0];
    const int*   ei = (const int*)d_in[1];
    int wb = n_in - 12;
    const float* W1 = (const float*)d_in[wb + 0];
    const float* b1 = (const float*)d_in[wb + 1];
    const float* W2 = (const float*)d_in[wb + 2];
    const float* b2 = (const float*)d_in[wb + 3];
    const float* W3 = (const float*)d_in[wb + 4];
    const float* b3 = (const float*)d_in[wb + 5];
    const float* W4 = (const float*)d_in[wb + 6];
    const float* b4 = (const float*)d_in[wb + 7];
    const float* W5 = (const float*)d_in[wb + 8];
    const float* b5 = (const float*)d_in[wb + 9];
    const float* Wl = (const float*)d_in[wb + 10];
    const float* bl = (const float*)d_in[wb + 11];
    float* out = (float*)d_out;

    int N = in_sizes[0] / 2;
    int E = in_sizes[1] / 2;
    const int* src = ei;
    const int* dst = ei + E;

    float *bufA, *bufB;
    cudaGetSymbolAddress((void**)&bufA, g_bufA);
    cudaGetSymbolAddress((void**)&bufB, g_bufB);
    int *degp, *fillp;
    cudaGetSymbolAddress((void**)&degp, g_deg);
    cudaGetSymbolAddress((void**)&fillp, g_fill);

    // ---- build normalized CSR (dst-sorted edges) ----
    cudaMemsetAsync(degp, 0, N * sizeof(int));
    cudaMemsetAsync(fillp, 0, N * sizeof(int));
    deg_kernel<<<(E + 255) / 256, 256>>>(dst, E);
    int NB = (N + 4095) / 4096;
    scan1_kernel<<<NB, 1024>>>(N);
    scan2_kernel<<<1, 32>>>(NB, N);
    scan3_kernel<<<(N + 1023) / 1024, 1024>>>(N);
    scatter_kernel<<<(E + 255) / 256, 256>>>(src, dst, E);

    // ---- layer 1: t = A x (F=2) ; x1 = relu(t W1 + b1) ----
    agg2_kernel<<<(N + 63) / 64, 128>>>(x, bufB, N);
    gemm_kernel<2, 128, 8, true, true><<<(N + 7) / 8, 128>>>(bufB, W1, b1, bufA, N);

    // ---- layer 2: t = A x1 (F=128) ; x2 = relu(t W2 + b2) ----
    agg4_kernel<128, false, false><<<(N + 3) / 4, 128>>>(bufA, bufB, nullptr, N);
    gemm_kernel<128, 128, 12, true, true><<<(N + 11) / 12, 128>>>(bufB, W2, b2, bufA, N);

    // ---- layer 3: t = x2 W3 (no bias) ; x3 = relu(A t + b3) (F=32) ----
    gemm_kernel<128, 32, 8, false, false><<<(N + 31) / 32, 128>>>(bufA, W3, nullptr, bufB, N);
    agg4_kernel<32, true, true><<<(N + 15) / 16, 128>>>(bufB, bufA, b3, N);

    // ---- layer 4: t = A x3 (F=32) ; x4 = relu(t W4 + b4) ----
    agg4_kernel<32, false, false><<<(N + 15) / 16, 128>>>(bufA, bufB, nullptr, N);
    gemm_kernel<32, 32, 8, true, true><<<(N + 31) / 32, 128>>>(bufB, W4, b4, bufA, N);

    // ---- layer 5: t = A x4 (F=32) ; x5 = relu(t W5 + b5) (F=64) ----
    agg4_kernel<32, false, false><<<(N + 15) / 16, 128>>>(bufA, bufB, nullptr, N);
    gemm_kernel<32, 64, 8, true, true><<<(N + 15) / 16, 128>>>(bufB, W5, b5, bufA, N);

    // ---- final linear 64 -> 1 ----
    linear_kernel<<<(N * 32 + 255) / 256, 256>>>(bufA, Wl, bl, out, N);
}

// round 5
// speedup vs baseline: 1.2483x; 1.2005x over previous
#include <cuda_runtime.h>
#include <cuda_fp16.h>

#define MAXN 100000
#define MAXE 1600000
#define MAXF 128

// ---------------- scratch (device globals; no cudaMalloc allowed) ----------------
__device__ float g_bufA[MAXN * MAXF];
__device__ float g_bufB[MAXN * MAXF];
__device__ int   g_deg[MAXN];
__device__ float g_dinv[MAXN];
__device__ int   g_rowptr[MAXN + 1];
__device__ int   g_fill[MAXN];
__device__ int2  g_edge[MAXE];          // (src, __float_as_int(norm))
__device__ int   g_blocksum[64];
__device__ int   g_blockoff[64];

// ---------------- preprocessing ----------------
__global__ void deg_kernel(const int* __restrict__ dst, int E) {
    int e = blockIdx.x * blockDim.x + threadIdx.x;
    if (e < E) atomicAdd(&g_deg[dst[e]], 1);
}

__global__ void scan1_kernel(int N) {
    const int T = 1024, EL = 4;
    int t = threadIdx.x;
    int base = blockIdx.x * (T * EL) + t * EL;
    int v[EL];
    int s = 0;
#pragma unroll
    for (int j = 0; j < EL; j++) {
        int i = base + j;
        v[j] = (i < N) ? g_deg[i] : 0;
        s += v[j];
    }
    __shared__ int sh[T];
    sh[t] = s;
    __syncthreads();
    for (int o = 1; o < T; o <<= 1) {
        int u = (t >= o) ? sh[t - o] : 0;
        __syncthreads();
        sh[t] += u;
        __syncthreads();
    }
    int run = (t == 0) ? 0 : sh[t - 1];
#pragma unroll
    for (int j = 0; j < EL; j++) {
        int i = base + j;
        if (i < N) g_rowptr[i] = run;
        run += v[j];
    }
    if (t == T - 1) g_blocksum[blockIdx.x] = sh[T - 1];
}

__global__ void scan2_kernel(int NB, int N) {
    int t = threadIdx.x;
    int x = (t < NB) ? g_blocksum[t] : 0;
    int v = x;
    for (int o = 1; o < 32; o <<= 1) {
        int u = __shfl_up_sync(0xFFFFFFFFu, v, o);
        if (t >= o) v += u;
    }
    if (t < NB) g_blockoff[t] = v - x;
    if (t == NB - 1) g_rowptr[N] = v;
}

__global__ void scan3_kernel(int N) {
    int i = blockIdx.x * blockDim.x + threadIdx.x;
    if (i < N) {
        g_rowptr[i] += g_blockoff[i >> 12];
        g_dinv[i] = rsqrtf((float)g_deg[i] + 1.0f);
    }
}

__global__ void scatter_kernel(const int* __restrict__ src, const int* __restrict__ dst, int E) {
    int e = blockIdx.x * blockDim.x + threadIdx.x;
    if (e >= E) return;
    int s = src[e], d = dst[e];
    int pos = g_rowptr[d] + atomicAdd(&g_fill[d], 1);
    g_edge[pos] = make_int2(s, __float_as_int(g_dinv[s] * g_dinv[d]));
}

// ---------------- GEMM (R2 scalar FFMA form): out = relu(in*W + b) ----------------
// OUT_HALF selects fp16 output storage (for activations consumed by aggregation).
template <int K, int F, int NPG, bool BIAS, bool RELU, bool OUT_HALF>
__global__ void __launch_bounds__(128) gemm_kernel(
        const float* __restrict__ in, const float* __restrict__ W,
        const float* __restrict__ b, void* __restrict__ outv, int N) {
    constexpr int GROUPS = 128 / F;
    constexpr int NT = NPG * GROUPS;
    __shared__ float sx[NT * K];
    int base = blockIdx.x * NT;
    for (int i = threadIdx.x; i < NT * K; i += 128) {
        int r = i / K, c = i % K;
        int n = base + r;
        sx[i] = (n < N) ? in[n * K + c] : 0.0f;
    }
    __syncthreads();
    int f = threadIdx.x % F;
    int g = threadIdx.x / F;
    float acc[NPG];
#pragma unroll
    for (int j = 0; j < NPG; j++) acc[j] = 0.0f;

    if constexpr (K % 4 == 0) {
        for (int k = 0; k < K; k += 4) {
            float w0 = W[(k + 0) * F + f];
            float w1 = W[(k + 1) * F + f];
            float w2 = W[(k + 2) * F + f];
            float w3 = W[(k + 3) * F + f];
#pragma unroll
            for (int j = 0; j < NPG; j++) {
                const float4 x4 = *reinterpret_cast<const float4*>(&sx[(g * NPG + j) * K + k]);
                acc[j] = fmaf(x4.x, w0, acc[j]);
                acc[j] = fmaf(x4.y, w1, acc[j]);
                acc[j] = fmaf(x4.z, w2, acc[j]);
                acc[j] = fmaf(x4.w, w3, acc[j]);
            }
        }
    } else {
        for (int k = 0; k < K; k++) {
            float wv = W[k * F + f];
#pragma unroll
            for (int j = 0; j < NPG; j++)
                acc[j] = fmaf(sx[(g * NPG + j) * K + k], wv, acc[j]);
        }
    }
    float bv = BIAS ? b[f] : 0.0f;
#pragma unroll
    for (int j = 0; j < NPG; j++) {
        int n = base + g * NPG + j;
        if (n < N) {
            float v = acc[j] + bv;
            if (RELU) v = fmaxf(v, 0.0f);
            if constexpr (OUT_HALF)
                ((__half*)outv)[n * F + f] = __float2half_rn(v);
            else
                ((float*)outv)[n * F + f] = v;
        }
    }
}

// ---------------- fp16-input aggregation: out = A*h (+b, relu opt) ----------------
// Each thread owns 8 features (one 16B uint4 of halves); fp32 accumulation.
__device__ __forceinline__ void cvt8(uint4 v, float* f) {
    float2 a = __half22float2(*(const __half2*)&v.x);
    float2 b = __half22float2(*(const __half2*)&v.y);
    float2 c = __half22float2(*(const __half2*)&v.z);
    float2 d = __half22float2(*(const __half2*)&v.w);
    f[0] = a.x; f[1] = a.y; f[2] = b.x; f[3] = b.y;
    f[4] = c.x; f[5] = c.y; f[6] = d.x; f[7] = d.y;
}

template <int F, bool BIAS, bool RELU, bool OUT_HALF>
__global__ void __launch_bounds__(128) aggh_kernel(
        const __half* __restrict__ h, void* __restrict__ outv,
        const float* __restrict__ b, int N) {
    constexpr int TPN = F / 8;            // threads per node (8 halves each)
    constexpr int NPB = 128 / TPN;
    int n = blockIdx.x * NPB + threadIdx.x / TPN;
    if (n >= N) return;
    int f8 = threadIdx.x % TPN;
    const uint4* __restrict__ h8 = (const uint4*)h;   // row stride = TPN uint4
    float di = g_dinv[n];
    float s0 = di * di;
    float acc0[8], acc1[8], t[8];
    cvt8(h8[n * TPN + f8], t);
#pragma unroll
    for (int i = 0; i < 8; i++) { acc0[i] = t[i] * s0; acc1[i] = 0.0f; }

    int beg = g_rowptr[n], end = g_rowptr[n + 1];
    int j = beg;
    for (; j + 1 < end; j += 2) {
        int2 eA = g_edge[j];
        int2 eB = g_edge[j + 1];
        uint4 va = h8[eA.x * TPN + f8];
        uint4 vb = h8[eB.x * TPN + f8];
        float nA = __int_as_float(eA.y);
        float nB = __int_as_float(eB.y);
        float ta[8], tb[8];
        cvt8(va, ta);
        cvt8(vb, tb);
#pragma unroll
        for (int i = 0; i < 8; i++) {
            acc0[i] = fmaf(ta[i], nA, acc0[i]);
            acc1[i] = fmaf(tb[i], nB, acc1[i]);
        }
    }
    if (j < end) {
        int2 eA = g_edge[j];
        uint4 va = h8[eA.x * TPN + f8];
        float nA = __int_as_float(eA.y);
        float ta[8];
        cvt8(va, ta);
#pragma unroll
        for (int i = 0; i < 8; i++) acc0[i] = fmaf(ta[i], nA, acc0[i]);
    }
    float r[8];
#pragma unroll
    for (int i = 0; i < 8; i++) r[i] = acc0[i] + acc1[i];
    if (BIAS) {
        const float4 b0 = *reinterpret_cast<const float4*>(b + f8 * 8);
        const float4 b1 = *reinterpret_cast<const float4*>(b + f8 * 8 + 4);
        r[0] += b0.x; r[1] += b0.y; r[2] += b0.z; r[3] += b0.w;
        r[4] += b1.x; r[5] += b1.y; r[6] += b1.z; r[7] += b1.w;
    }
    if (RELU) {
#pragma unroll
        for (int i = 0; i < 8; i++) r[i] = fmaxf(r[i], 0.0f);
    }
    if constexpr (OUT_HALF) {
        uint4 o;
        *(__half2*)&o.x = __float22half2_rn(make_float2(r[0], r[1]));
        *(__half2*)&o.y = __float22half2_rn(make_float2(r[2], r[3]));
        *(__half2*)&o.z = __float22half2_rn(make_float2(r[4], r[5]));
        *(__half2*)&o.w = __float22half2_rn(make_float2(r[6], r[7]));
        ((uint4*)outv)[n * TPN + f8] = o;
    } else {
        float* outf = (float*)outv;
        *reinterpret_cast<float4*>(outf + n * F + f8 * 8) =
            make_float4(r[0], r[1], r[2], r[3]);
        *reinterpret_cast<float4*>(outf + n * F + f8 * 8 + 4) =
            make_float4(r[4], r[5], r[6], r[7]);
    }
}

// scalar aggregation for F=2 (layer-1 input, fp32)
__global__ void agg2_kernel(const float* __restrict__ h, float* __restrict__ out, int N) {
    int n = blockIdx.x * 64 + threadIdx.x / 2;
    if (n >= N) return;
    int f = threadIdx.x % 2;
    float di = g_dinv[n];
    float acc = h[n * 2 + f] * di * di;
    int beg = g_rowptr[n], end = g_rowptr[n + 1];
    for (int j = beg; j < end; j++) {
        int2 e = g_edge[j];
        acc = fmaf(h[e.x * 2 + f], __int_as_float(e.y), acc);
    }
    out[n * 2 + f] = acc;
}

// ---------------- final linear: out[n] = x[n,0:64] . Wl + bl ----------------
__global__ void linear_kernel(const float* __restrict__ x, const float* __restrict__ Wl,
                              const float* __restrict__ bl, float* __restrict__ out, int N) {
    int warp = (blockIdx.x * blockDim.x + threadIdx.x) >> 5;
    int lane = threadIdx.x & 31;
    if (warp >= N) return;
    float v = x[warp * 64 + lane] * Wl[lane] + x[warp * 64 + 32 + lane] * Wl[32 + lane];
#pragma unroll
    for (int o = 16; o; o >>= 1) v += __shfl_xor_sync(0xFFFFFFFFu, v, o);
    if (lane == 0) out[warp] = v + bl[0];
}

// ---------------- launch ----------------
extern "C" void kernel_launch(void* const* d_in, const int* in_sizes, int n_in,
                              void* d_out, int out_size) {
    const float* x  = (const float*)d_in[0];
    const int*   ei = (const int*)d_in[1];
    int wb = n_in - 12;
    const float* W1 = (const float*)d_in[wb + 0];
    const float* b1 = (const float*)d_in[wb + 1];
    const float* W2 = (const float*)d_in[wb + 2];
    const float* b2 = (const float*)d_in[wb + 3];
    const float* W3 = (const float*)d_in[wb + 4];
    const float* b3 = (const float*)d_in[wb + 5];
    const float* W4 = (const float*)d_in[wb + 6];
    const float* b4 = (const float*)d_in[wb + 7];
    const float* W5 = (const float*)d_in[wb + 8];
    const float* b5 = (const float*)d_in[wb + 9];
    const float* Wl = (const float*)d_in[wb + 10];
    const float* bl = (const float*)d_in[wb + 11];
    float* out = (float*)d_out;

    int N = in_sizes[0] / 2;
    int E = in_sizes[1] / 2;
    const int* src = ei;
    const int* dst = ei + E;

    float *bufA, *bufB;
    cudaGetSymbolAddress((void**)&bufA, g_bufA);
    cudaGetSymbolAddress((void**)&bufB, g_bufB);
    __half* hbufA = (__half*)bufA;
    __half* hbufB = (__half*)bufB;
    int *degp, *fillp;
    cudaGetSymbolAddress((void**)&degp, g_deg);
    cudaGetSymbolAddress((void**)&fillp, g_fill);

    // ---- build normalized CSR (dst-sorted edges) ----
    cudaMemsetAsync(degp, 0, N * sizeof(int));
    cudaMemsetAsync(fillp, 0, N * sizeof(int));
    deg_kernel<<<(E + 255) / 256, 256>>>(dst, E);
    int NB = (N + 4095) / 4096;
    scan1_kernel<<<NB, 1024>>>(N);
    scan2_kernel<<<1, 32>>>(NB, N);
    scan3_kernel<<<(N + 1023) / 1024, 1024>>>(N);
    scatter_kernel<<<(E + 255) / 256, 256>>>(src, dst, E);

    // ---- layer 1: t = A x (F=2, fp32) ; x1 = relu(t W1 + b1)  -> half ----
    agg2_kernel<<<(N + 63) / 64, 128>>>(x, bufB, N);
    gemm_kernel<2, 128, 8, true, true, true><<<(N + 7) / 8, 128>>>(bufB, W1, b1, hbufA, N);

    // ---- layer 2: t = A x1 (half in, fp32 out) ; x2 = relu(t W2 + b2) (fp32) ----
    aggh_kernel<128, false, false, false><<<(N + 7) / 8, 128>>>(hbufA, bufB, nullptr, N);
    gemm_kernel<128, 128, 16, true, true, false><<<(N + 15) / 16, 128>>>(bufB, W2, b2, bufA, N);

    // ---- layer 3: t3 = x2 W3 (half out) ; x3 = relu(A t3 + b3) (half out) ----
    gemm_kernel<128, 32, 8, false, false, true><<<(N + 31) / 32, 128>>>(bufA, W3, nullptr, hbufB, N);
    aggh_kernel<32, true, true, true><<<(N + 31) / 32, 128>>>(hbufB, hbufA, b3, N);

    // ---- layer 4: t4 = A x3 (fp32 out) ; x4 = relu(t4 W4 + b4) (half out) ----
    aggh_kernel<32, false, false, false><<<(N + 31) / 32, 128>>>(hbufA, bufB, nullptr, N);
    gemm_kernel<32, 32, 8, true, true, true><<<(N + 31) / 32, 128>>>(bufB, W4, b4, hbufB, N);

    // ---- layer 5: t5 = A x4 (fp32 out) ; x5 = relu(t5 W5 + b5) (fp32) ----
    aggh_kernel<32, false, false, false><<<(N + 31) / 32, 128>>>(hbufB, bufA, nullptr, N);
    gemm_kernel<32, 64, 8, true, true, false><<<(N + 15) / 16, 128>>>(bufA, W5, b5, bufB, N);

    // ---- final linear 64 -> 1 ----
    linear_kernel<<<(N * 32 + 255) / 256, 256>>>(bufB, Wl, bl, out, N);
}